// round 15
// baseline (speedup 1.0000x reference)
#include <cuda_runtime.h>
#include <cuda_bf16.h>
#include <cstdint>

// h_new[n, j] = h_prev[n, j] + sum_k W[Z[n]][j][k] * m_curr[n][k]
// N = 16384, D = 128, S = 119, atom_types sorted.
//
// Round 13: fully-async pipeline.
//  - All gmem->smem via cp.async.cg: m tile, h_prev tile (prefetched at start),
//    W in 32-col k-chunks, double-buffered (chunk c+2 in flight during MMA c).
//  - Raw fp32 bits into mma.sync.tf32 (HW truncation) -- no cvt pass.
//  - Segment table (start indices) built once with ballots/popcounts; chunk
//    stream = nseg*4 chunks, uniform (seg, kc) = (c>>2, c&3).

#define N_NODES  16384
#define D        128
#define NB       64
#define THREADS  256
#define PM       132        // m/h smem pitch (floats): 132 % 32 == 4 -> conflict-free
#define PW       36         // W chunk pitch (floats):  36 % 32 == 4 -> conflict-free

// smem layout (bytes)
#define M_OFF    0
#define W_OFF    (NB * PM * 4)                  // 33792
#define H_OFF    (W_OFF + 2 * D * PW * 4)       // 33792 + 36864 = 70656
#define TY_OFF   (H_OFF + NB * PM * 4)          // +33792 = 104448
#define SG_OFF   (TY_OFF + NB * 4)              // 104704  (segs[65])
#define MK_OFF   (SG_OFF + 65 * 4)              // 104964
#define SMEM_TOTAL (MK_OFF + 8)

__device__ __forceinline__ void cp16(uint32_t dst, const void* src) {
    asm volatile("cp.async.cg.shared.global [%0], [%1], 16;"
                 :: "r"(dst), "l"(src) : "memory");
}
#define CP_COMMIT() asm volatile("cp.async.commit_group;" ::: "memory")
#define CP_WAIT(N)  asm volatile("cp.async.wait_group %0;" :: "n"(N) : "memory")

__device__ __forceinline__ void mma_tf32(float& c0, float& c1, float& c2, float& c3,
                                         uint32_t a0, uint32_t a1, uint32_t a2, uint32_t a3,
                                         uint32_t b0, uint32_t b1) {
    asm volatile(
        "mma.sync.aligned.m16n8k8.row.col.f32.tf32.tf32.f32 "
        "{%0,%1,%2,%3}, {%4,%5,%6,%7}, {%8,%9}, {%0,%1,%2,%3};"
        : "+f"(c0), "+f"(c1), "+f"(c2), "+f"(c3)
        : "r"(a0), "r"(a1), "r"(a2), "r"(a3), "r"(b0), "r"(b1));
}

__global__ void __launch_bounds__(THREADS, 2)
element_update_kernel(const float* __restrict__ h_prev,
                      const float* __restrict__ m_curr,
                      const int*   __restrict__ atom_types,
                      const float* __restrict__ weight,
                      float*       __restrict__ out)
{
    extern __shared__ char smem[];
    uint32_t sbase;
    asm("{ .reg .u64 t; cvta.to.shared.u64 t, %1; cvt.u32.u64 %0, t; }"
        : "=r"(sbase) : "l"(smem));

    const uint32_t* m_u   = (const uint32_t*)(smem + M_OFF);
    const uint32_t* w_u   = (const uint32_t*)(smem + W_OFF);
    const float*    h_f   = (const float*)(smem + H_OFF);
    int*            types = (int*)(smem + TY_OFF);
    int*            segs  = (int*)(smem + SG_OFF);
    unsigned*       masks = (unsigned*)(smem + MK_OFF);

    const int t    = threadIdx.x;
    const int warp = t >> 5;
    const int lane = t & 31;
    const int qr   = lane >> 2;
    const int qc   = lane & 3;
    const int m0   = (warp & 3) * 16;
    const int nc0  = (warp >> 2) * 64;
    const int n0   = blockIdx.x * NB;

    const int z0 = atom_types[n0];

    // ---- issue W chunk (c) helper state in lambda form via macro ----
    // chunk c: seg = c>>2, kc = c&3, buffer = c&1
#define ISSUE_CHUNK(c_, z_) do {                                               \
        const int kc_ = (c_) & 3;                                              \
        const float* wz_ = weight + (size_t)(z_) * D * D + kc_ * 32;           \
        const uint32_t wb_ = sbase + W_OFF + (uint32_t)(((c_) & 1) * D * PW * 4); \
        _Pragma("unroll")                                                      \
        for (int q = 0; q < 4; q++) {                                          \
            int unit = t + q * THREADS;        /* 0..1023 */                   \
            int row = unit >> 3, u = unit & 7;                                 \
            cp16(wb_ + (uint32_t)((row * PW + u * 4) * 4), wz_ + row * D + u * 4); \
        }                                                                      \
        CP_COMMIT();                                                           \
    } while (0)

    // ---- group 0: m tile + h_prev tile + W chunk 0 ----
    {
        #pragma unroll
        for (int q = 0; q < 8; q++) {
            int unit = t + q * THREADS;        // 0..2047
            int row = unit >> 5, u = unit & 31;
            cp16(sbase + M_OFF + (uint32_t)((row * PM + u * 4) * 4),
                 m_curr + (size_t)(n0 + row) * D + u * 4);
        }
        #pragma unroll
        for (int q = 0; q < 8; q++) {
            int unit = t + q * THREADS;
            int row = unit >> 5, u = unit & 31;
            cp16(sbase + H_OFF + (uint32_t)((row * PM + u * 4) * 4),
                 h_prev + (size_t)(n0 + row) * D + u * 4);
        }
        const float* wz = weight + (size_t)z0 * D * D;
        #pragma unroll
        for (int q = 0; q < 4; q++) {
            int unit = t + q * THREADS;
            int row = unit >> 3, u = unit & 7;
            cp16(sbase + W_OFF + (uint32_t)((row * PW + u * 4) * 4),
                 wz + row * D + u * 4);
        }
        CP_COMMIT();
    }
    // ---- group 1: W chunk 1 (still segment 0) ----
    ISSUE_CHUNK(1, z0);

    // ---- types + segment table (overlaps the async loads) ----
    int myty = 0, flag = 0;
    if (t < NB) {
        myty = atom_types[n0 + t];
        types[t] = myty;
        int prev = (t == 0) ? (myty + 1) : atom_types[n0 + t - 1];
        flag = (prev != myty);
        unsigned b = __ballot_sync(0xffffffffu, flag);
        if (lane == 0) masks[warp] = b;
    }
    __syncthreads();                     // masks + types visible
    const unsigned mm0 = masks[0], mm1 = masks[1];
    const int nseg = __popc(mm0) + __popc(mm1);
    if (t < NB && flag) {
        int rank = (t < 32) ? __popc(mm0 & ((1u << lane) - 1))
                            : __popc(mm0) + __popc(mm1 & ((1u << lane) - 1));
        segs[rank] = t;
    }
    if (t == 0) segs[nseg] = NB;
    const int nchunks = nseg * 4;

    CP_WAIT(1);                          // group0 (m, h, chunk0) arrived
    __syncthreads();                     // segs + smem data visible to all

    // ---- accumulators ----
    float acc[8][4];
    #pragma unroll
    for (int nt = 0; nt < 8; nt++)
        #pragma unroll
        for (int q = 0; q < 4; q++) acc[nt][q] = 0.0f;

    const int r0 = m0 + qr, r1 = r0 + 8;

    // ---- chunk loop ----
    for (int c = 0; c < nchunks; c++) {
        const int seg = c >> 2, kc = c & 3;
        const int s = segs[seg], e = segs[seg + 1];

        if (e > m0 && s < m0 + 16) {
            const bool p0 = (r0 >= s) & (r0 < e);
            const bool p1 = (r1 >= s) & (r1 < e);
            const uint32_t* mr0 = m_u + r0 * PM + kc * 32;
            const uint32_t* mr1 = m_u + r1 * PM + kc * 32;
            const uint32_t* wb  = w_u + (c & 1) * D * PW;

            #pragma unroll
            for (int ks = 0; ks < 4; ks++) {
                const int k0l = ks * 8;
                uint32_t a0 = p0 ? mr0[k0l + qc]     : 0u;
                uint32_t a1 = p1 ? mr1[k0l + qc]     : 0u;
                uint32_t a2 = p0 ? mr0[k0l + qc + 4] : 0u;
                uint32_t a3 = p1 ? mr1[k0l + qc + 4] : 0u;
                #pragma unroll
                for (int nt = 0; nt < 8; nt++) {
                    const uint32_t* wr = wb + (nc0 + nt * 8 + qr) * PW + k0l;
                    mma_tf32(acc[nt][0], acc[nt][1], acc[nt][2], acc[nt][3],
                             a0, a1, a2, a3, wr[qc], wr[qc + 4]);
                }
            }
        }
        __syncthreads();                 // mma(c) readers done with buffer c&1

        if (c + 2 < nchunks) {
            const int zc = types[segs[(c + 2) >> 2]];
            ISSUE_CHUNK(c + 2, zc);
            CP_WAIT(1);                  // chunk c+1 ready
        } else if (c + 1 < nchunks) {
            CP_WAIT(0);
        }
        if (c + 1 < nchunks) __syncthreads();
    }

    // ---- epilogue: h from smem, add, store ----
    #pragma unroll
    for (int nt = 0; nt < 8; nt++) {
        const int col = nc0 + nt * 8 + qc * 2;
        const size_t ia = (size_t)(n0 + r0) * D + col;
        const size_t ib = (size_t)(n0 + r1) * D + col;
        float2 ha = *(const float2*)(h_f + r0 * PM + col);
        float2 hb = *(const float2*)(h_f + r1 * PM + col);
        *(float2*)(out + ia) = make_float2(ha.x + acc[nt][0], ha.y + acc[nt][1]);
        *(float2*)(out + ib) = make_float2(hb.x + acc[nt][2], hb.y + acc[nt][3]);
    }
}

extern "C" void kernel_launch(void* const* d_in, const int* in_sizes, int n_in,
                              void* d_out, int out_size)
{
    const float* h_prev     = (const float*)d_in[0];
    const float* m_curr     = (const float*)d_in[1];
    const int*   atom_types = (const int*)  d_in[2];
    const float* weight     = (const float*)d_in[3];
    float*       out        = (float*)d_out;

    cudaFuncSetAttribute(element_update_kernel,
                         cudaFuncAttributeMaxDynamicSharedMemorySize, SMEM_TOTAL);
    dim3 grid(N_NODES / NB);   // 256 blocks
    dim3 block(THREADS);
    element_update_kernel<<<grid, block, SMEM_TOTAL>>>(h_prev, m_curr, atom_types,
                                                       weight, out);
}